// round 3
// baseline (speedup 1.0000x reference)
#include <cuda_runtime.h>

#define OH 121          // output patches per dim: 128 - 8 + 1
#define NIMG 8

// ---------------- device scratch (no allocations allowed) ----------------
__device__ float g_S[256 * 256];                    // LISTA mutual-inhibition matrix (tf32-rounded)
__device__ float g_XP[NIMG * 128 * 128 * 64];       // x_pred per (img, pr, pc, d) ~33.5MB

// ---------------- packed fp32x2 helpers (full-rate FMA on Blackwell) -----
static __device__ __forceinline__ unsigned long long pk2(float lo, float hi) {
    unsigned long long r;
    unsigned int l = __float_as_uint(lo), h = __float_as_uint(hi);
    asm("mov.b64 %0, {%1,%2};" : "=l"(r) : "r"(l), "r"(h));
    return r;
}
static __device__ __forceinline__ void upk2(unsigned long long v, float& lo, float& hi) {
    unsigned int l, h;
    asm("mov.b64 {%0,%1}, %2;" : "=r"(l), "=r"(h) : "l"(v));
    lo = __uint_as_float(l); hi = __uint_as_float(h);
}
static __device__ __forceinline__ void fma2(unsigned long long& d,
                                            unsigned long long a, unsigned long long b) {
    asm("fma.rn.f32x2 %0, %1, %2, %0;" : "+l"(d) : "l"(a), "l"(b));
}

// TF32 rounding (emulate XLA/cuBLAS tf32 matmul operand rounding)
static __device__ __forceinline__ float tf32r(float v) {
    unsigned int r;
    asm("cvt.rna.tf32.f32 %0, %1;" : "=r"(r) : "f"(v));
    return __uint_as_float(r);
}

static __device__ __forceinline__ float softthr(float v, float t) {
    float r = fmaxf(fabsf(v) - t, 0.0f);
    float s = (v > 0.0f) ? 1.0f : ((v < 0.0f) ? -1.0f : 0.0f);   // exact sign(0)=0
    return s * r;
}

// ---------------- kernel 1: S = tf32( I - (D^T D)/c ), D^T D in tf32 -----
__global__ void sprep_kernel(const float* __restrict__ Dict, const float* __restrict__ cp) {
    int k = blockIdx.x, n = threadIdx.x;
    float c = cp[0];
    float s = 0.0f;
#pragma unroll 8
    for (int r = 0; r < 64; r++)
        s = fmaf(tf32r(Dict[r * 256 + k]), tf32r(Dict[r * 256 + n]), s);
    g_S[k * 256 + n] = tf32r((k == n ? 1.0f : 0.0f) - s / c);
}

// ---------------- kernel 2: per-tile LISTA pipeline ----------------------
// CTA: 8x8 patch block of one image (64 patches), 256 threads.
// smem: U 16KB | scr 32KB (h1/h3/S-chunk) | yc 64KB (h2/y/c/DictT) | z 64KB | thr
__global__ __launch_bounds__(256, 1) void lista_kernel(
    const float* __restrict__ x, const float* __restrict__ Dict,
    const float* __restrict__ cp, const float* __restrict__ wp,
    const float* __restrict__ W1, const float* __restrict__ b1,
    const float* __restrict__ W2, const float* __restrict__ b2,
    const float* __restrict__ W3, const float* __restrict__ b3,
    const float* __restrict__ W4, const float* __restrict__ b4)
{
    extern __shared__ float sm[];
    float* U   = sm;              // 64*64   = 4096
    float* scr = sm + 4096;       // 64*128  = 8192
    float* yc  = sm + 12288;      // 64*256  = 16384
    float* z   = sm + 28672;      // 64*256  = 16384
    float* thr = sm + 45056;      // 64

    const int tid = threadIdx.x;
    const int img = blockIdx.z;
    const int pr0 = blockIdx.y * 8, pc0 = blockIdx.x * 8;
    const float c = cp[0], cinv = 1.0f / c, wv = wp[0];
    const float* xi = x + img * 16384;

    // ---- build U (zero-fill invalid patches), tf32-rounded (matmul operand only)
    for (int idx = tid; idx < 4096; idx += 256) {
        int m = idx >> 6, d = idx & 63;
        int pr = pr0 + (m >> 3), pc = pc0 + (m & 7);
        float v = 0.0f;
        if (pr < OH && pc < OH) v = xi[(pr + (d >> 3)) * 128 + pc + (d & 7)];
        U[idx] = tf32r(v);
    }
    __syncthreads();

    // ---- MLP stage A: h1[64][128] = relu(U@W1+b1) -> scr (tf32-rounded) ----
    {
        int j = tid & 127;
        int mbase = tid >> 7;   // 0..1, m = mbase + 2t
        float acc[32];
#pragma unroll
        for (int t = 0; t < 32; t++) acc[t] = 0.0f;
        for (int r0 = 0; r0 < 64; r0 += 16) {
            float wc[16];
#pragma unroll
            for (int rr = 0; rr < 16; rr++) wc[rr] = tf32r(W1[(r0 + rr) * 128 + j]);
#pragma unroll
            for (int t = 0; t < 32; t++) {
                const float4* up = (const float4*)(U + (mbase + 2 * t) * 64 + r0);
#pragma unroll
                for (int q4 = 0; q4 < 4; q4++) {
                    float4 u = up[q4];
                    acc[t] = fmaf(u.x, wc[q4 * 4 + 0], acc[t]);
                    acc[t] = fmaf(u.y, wc[q4 * 4 + 1], acc[t]);
                    acc[t] = fmaf(u.z, wc[q4 * 4 + 2], acc[t]);
                    acc[t] = fmaf(u.w, wc[q4 * 4 + 3], acc[t]);
                }
            }
        }
        float bb = b1[j];
#pragma unroll
        for (int t = 0; t < 32; t++)
            scr[(mbase + 2 * t) * 128 + j] = tf32r(fmaxf(acc[t] + bb, 0.0f));
    }
    __syncthreads();

    // ---- MLP stage B: h2[64][64] = relu(h1@W2+b2) -> yc[0:4096) (tf32) ----
    {
        int j = tid & 63;
        int mbase = tid >> 6;   // 0..3, m = mbase + 4t
        float acc[16];
#pragma unroll
        for (int t = 0; t < 16; t++) acc[t] = 0.0f;
        for (int r0 = 0; r0 < 128; r0 += 16) {
            float wc[16];
#pragma unroll
            for (int rr = 0; rr < 16; rr++) wc[rr] = tf32r(W2[(r0 + rr) * 64 + j]);
#pragma unroll
            for (int t = 0; t < 16; t++) {
                const float4* hp = (const float4*)(scr + (mbase + 4 * t) * 128 + r0);
#pragma unroll
                for (int q4 = 0; q4 < 4; q4++) {
                    float4 u = hp[q4];
                    acc[t] = fmaf(u.x, wc[q4 * 4 + 0], acc[t]);
                    acc[t] = fmaf(u.y, wc[q4 * 4 + 1], acc[t]);
                    acc[t] = fmaf(u.z, wc[q4 * 4 + 2], acc[t]);
                    acc[t] = fmaf(u.w, wc[q4 * 4 + 3], acc[t]);
                }
            }
        }
        float bb = b2[j];
#pragma unroll
        for (int t = 0; t < 16; t++)
            yc[(mbase + 4 * t) * 64 + j] = tf32r(fmaxf(acc[t] + bb, 0.0f));
    }
    __syncthreads();

    // ---- MLP stage C: h3[64][32] = relu(h2@W3+b3) -> scr[0:2048) (tf32) ----
    {
        int j = tid & 31;
        int mbase = tid >> 5;   // 0..7, m = mbase + 8t
        float acc[8];
#pragma unroll
        for (int t = 0; t < 8; t++) acc[t] = 0.0f;
        for (int r0 = 0; r0 < 64; r0 += 16) {
            float wc[16];
#pragma unroll
            for (int rr = 0; rr < 16; rr++) wc[rr] = tf32r(W3[(r0 + rr) * 32 + j]);
#pragma unroll
            for (int t = 0; t < 8; t++) {
                const float4* hp = (const float4*)(yc + (mbase + 8 * t) * 64 + r0);
#pragma unroll
                for (int q4 = 0; q4 < 4; q4++) {
                    float4 u = hp[q4];
                    acc[t] = fmaf(u.x, wc[q4 * 4 + 0], acc[t]);
                    acc[t] = fmaf(u.y, wc[q4 * 4 + 1], acc[t]);
                    acc[t] = fmaf(u.z, wc[q4 * 4 + 2], acc[t]);
                    acc[t] = fmaf(u.w, wc[q4 * 4 + 3], acc[t]);
                }
            }
        }
        float bb = b3[j];
#pragma unroll
        for (int t = 0; t < 8; t++)
            scr[(mbase + 8 * t) * 32 + j] = tf32r(fmaxf(acc[t] + bb, 0.0f));
    }
    __syncthreads();

    // ---- MLP stage D: thr = (h3@W4+b4)/c ----
    if (tid < 64) {
        const float* hm = scr + tid * 32;
        float a = b4[0];
#pragma unroll
        for (int r = 0; r < 32; r++) a = fmaf(hm[r], tf32r(W4[r]), a);
        thr[tid] = a / c;   // IEEE divide, matches reference lam/c
    }
    __syncthreads();

    // ---- y = U@Dict ; yc = y/c ; z0 = tf32(soft(y, thr)) ----
    {
        int n = tid;  // one atom column per thread
        for (int m0 = 0; m0 < 64; m0 += 8) {
            float acc[8];
#pragma unroll
            for (int i = 0; i < 8; i++) acc[i] = 0.0f;
#pragma unroll 4
            for (int r0 = 0; r0 < 64; r0 += 4) {
                float dv0 = tf32r(Dict[(r0 + 0) * 256 + n]);
                float dv1 = tf32r(Dict[(r0 + 1) * 256 + n]);
                float dv2 = tf32r(Dict[(r0 + 2) * 256 + n]);
                float dv3 = tf32r(Dict[(r0 + 3) * 256 + n]);
#pragma unroll
                for (int i = 0; i < 8; i++) {
                    float4 u = *(const float4*)(U + (m0 + i) * 64 + r0);
                    acc[i] = fmaf(u.x, dv0, acc[i]);
                    acc[i] = fmaf(u.y, dv1, acc[i]);
                    acc[i] = fmaf(u.z, dv2, acc[i]);
                    acc[i] = fmaf(u.w, dv3, acc[i]);
                }
            }
#pragma unroll
            for (int i = 0; i < 8; i++) {
                int m = m0 + i;
                float yv = acc[i];
                z[m * 256 + n]  = tf32r(softthr(yv, thr[m]));
                yc[m * 256 + n] = yv * cinv;   // additive term, stays fp32
            }
        }
    }
    __syncthreads();   // yc/z fully written before cross-thread reads (race fix)

    // ---- LISTA main loop: z = soft(z@S + y/c, thr), x7 -----------------
    // z and S are tf32-rounded at their store points -> tf32-emulated matmul,
    // fp32 accumulate. Zero extra ops in this hot loop.
    const int tx = tid & 15, ty = tid >> 4;
    for (int it = 0; it < 7; it++) {
        unsigned long long acc[4][8];
#pragma unroll
        for (int i = 0; i < 4; i++) {
            const float4* yr = (const float4*)(yc + (ty * 4 + i) * 256 + tx * 16);
#pragma unroll
            for (int jj = 0; jj < 4; jj++) {
                float4 v = yr[jj];
                acc[i][2 * jj]     = pk2(v.x, v.y);
                acc[i][2 * jj + 1] = pk2(v.z, v.w);
            }
        }
        for (int k0 = 0; k0 < 256; k0 += 32) {
            __syncthreads();   // previous chunk readers / z writers done
            {
                const float4* src = (const float4*)(g_S + k0 * 256);
                float4* dst = (float4*)scr;
#pragma unroll
                for (int t2 = 0; t2 < 8; t2++) dst[tid + t2 * 256] = src[tid + t2 * 256];
            }
            __syncthreads();
#pragma unroll 2
            for (int k = 0; k < 32; k++) {
                unsigned long long sv[8];
                const float4* srow = (const float4*)(scr + k * 256 + tx * 16);
#pragma unroll
                for (int jj = 0; jj < 4; jj++) {
                    float4 v = srow[jj];
                    sv[2 * jj]     = pk2(v.x, v.y);
                    sv[2 * jj + 1] = pk2(v.z, v.w);
                }
#pragma unroll
                for (int i = 0; i < 4; i++) {
                    float zr = z[(ty * 4 + i) * 256 + k0 + k];
                    unsigned long long zz = pk2(zr, zr);
#pragma unroll
                    for (int j = 0; j < 8; j++) fma2(acc[i][j], zz, sv[j]);
                }
            }
        }
        __syncthreads();   // all reads of z complete before overwrite
#pragma unroll
        for (int i = 0; i < 4; i++) {
            int m = ty * 4 + i;
            float t = thr[m];
            float* zr = z + m * 256 + tx * 16;
#pragma unroll
            for (int j = 0; j < 8; j++) {
                float lo, hi;
                upk2(acc[i][j], lo, hi);
                zr[2 * j]     = tf32r(softthr(lo, t));
                zr[2 * j + 1] = tf32r(softthr(hi, t));
            }
        }
    }
    __syncthreads();

    // ---- stage Dict^T into yc: DT[k][d] = tf32(Dict[d][k]) ----
    for (int idx = tid; idx < 16384; idx += 256) {
        int d = idx >> 8, k = idx & 255;
        yc[k * 64 + d] = tf32r(Dict[idx]);
    }
    __syncthreads();

    // ---- x_pred = clip(z @ Dict^T, 0, 1) * w -> g_XP ----
    {
        // thread tile: 4 rows (ty) x 4 d-cols (tx*4), f32x2 pairs
        unsigned long long acc[4][2];
#pragma unroll
        for (int i = 0; i < 4; i++) { acc[i][0] = 0ull; acc[i][1] = 0ull; }
#pragma unroll 4
        for (int k = 0; k < 256; k++) {
            float4 v = *(const float4*)(yc + k * 64 + tx * 4);
            unsigned long long d01 = pk2(v.x, v.y), d23 = pk2(v.z, v.w);
#pragma unroll
            for (int i = 0; i < 4; i++) {
                float zr = z[(ty * 4 + i) * 256 + k];
                unsigned long long zz = pk2(zr, zr);
                fma2(acc[i][0], zz, d01);
                fma2(acc[i][1], zz, d23);
            }
        }
#pragma unroll
        for (int i = 0; i < 4; i++) {
            int m = ty * 4 + i;
            int pr = pr0 + (m >> 3), pc = pc0 + (m & 7);
            if (pr >= OH || pc >= OH) continue;
            float v0, v1, v2, v3;
            upk2(acc[i][0], v0, v1);
            upk2(acc[i][1], v2, v3);
            float4 o;
            o.x = fminf(fmaxf(v0, 0.0f), 1.0f) * wv;
            o.y = fminf(fmaxf(v1, 0.0f), 1.0f) * wv;
            o.z = fminf(fmaxf(v2, 0.0f), 1.0f) * wv;
            o.w = fminf(fmaxf(v3, 0.0f), 1.0f) * wv;
            int gp = img * 16384 + pr * 128 + pc;
            *(float4*)(g_XP + (size_t)gp * 64 + tx * 4) = o;
        }
    }
}

// ---------------- kernel 3: gather fold + analytic denominator -----------
__global__ void finalize_kernel(float* __restrict__ out, const float* __restrict__ wp) {
    int idx = blockIdx.x * 256 + threadIdx.x;           // 131072 pixels
    int img = idx >> 14, i = (idx >> 7) & 127, j = idx & 127;
    float s = 0.0f;
#pragma unroll
    for (int di = 0; di < 8; di++) {
        int pr = i - di;
        if (pr < 0 || pr >= OH) continue;
#pragma unroll
        for (int dj = 0; dj < 8; dj++) {
            int pc = j - dj;
            if (pc < 0 || pc >= OH) continue;
            s += g_XP[(size_t)(img * 16384 + pr * 128 + pc) * 64 + di * 8 + dj];
        }
    }
    int ci = min(min(i + 1, 8), 128 - i);
    int cj = min(min(j + 1, 8), 128 - j);
    out[idx] = s / (wp[0] * (float)(ci * cj));
}

// ---------------- launch ----------------
extern "C" void kernel_launch(void* const* d_in, const int* in_sizes, int n_in,
                              void* d_out, int out_size) {
    const float* x    = (const float*)d_in[0];
    const float* Dict = (const float*)d_in[1];
    const float* c    = (const float*)d_in[2];
    const float* w    = (const float*)d_in[3];
    const float* W1   = (const float*)d_in[4];
    const float* b1   = (const float*)d_in[5];
    const float* W2   = (const float*)d_in[6];
    const float* b2   = (const float*)d_in[7];
    const float* W3   = (const float*)d_in[8];
    const float* b3   = (const float*)d_in[9];
    const float* W4   = (const float*)d_in[10];
    const float* b4   = (const float*)d_in[11];
    float* out = (float*)d_out;

    const int SMEM_BYTES = 45120 * 4;   // 176.25 KB dynamic smem
    cudaFuncSetAttribute(lista_kernel, cudaFuncAttributeMaxDynamicSharedMemorySize, SMEM_BYTES);

    sprep_kernel<<<256, 256>>>(Dict, c);
    lista_kernel<<<dim3(16, 16, NIMG), 256, SMEM_BYTES>>>(
        x, Dict, c, w, W1, b1, W2, b2, W3, b3, W4, b4);
    finalize_kernel<<<512, 256>>>(out, w);
}

// round 5
// speedup vs baseline: 6.8033x; 6.8033x over previous
#include <cuda_runtime.h>

#define OH 121
#define NIMG 8

#define LDA 324                 // A stride (floats), 324 % 32 == 4 -> conflict-free frags
#define ABASE_U 256             // U lives at A cols [256,320)
#define SM_BBUF 41472           // 128*324 floats of A
#define BBUF_STRIDE 4224        // 16 * 264 floats (max-N chunk buffer)
#define SM_BIAS 49920           // b1[128] b2[64] b3[32] w4[32] thr[128]
#define SM_FLOATS 50304
#define SMEM_BYTES (SM_FLOATS * 4)

// ---------------- device scratch (B operands, tf32-pre-rounded, [K][N] row-major) ----
__device__ __align__(16) float g_Bls[320 * 256];  // [S ; Dict/c]  (K=320, N=256)
__device__ __align__(16) float g_Bh1[64 * 128];   // W1            (K=64,  N=128)
__device__ __align__(16) float g_Bh2[128 * 64];   // W2            (K=128, N=64)
__device__ __align__(16) float g_Bh3[64 * 32];    // W3            (K=64,  N=32)
__device__ __align__(16) float g_By [64 * 256];   // Dict          (K=64,  N=256)
__device__ __align__(16) float g_Bxp[256 * 64];   // Dict^T        (K=256, N=64)
__device__ float g_XP[NIMG * 128 * 128 * 64];     // x_pred patches

// ---------------- helpers ----------------
static __device__ __forceinline__ float tf32r(float v) {
    unsigned r;
    asm("cvt.rna.tf32.f32 %0, %1;" : "=r"(r) : "f"(v));
    return __uint_as_float(r);
}
static __device__ __forceinline__ float softthr(float v, float t) {
    float r = fmaxf(fabsf(v) - t, 0.0f);
    float s = (v > 0.0f) ? 1.0f : ((v < 0.0f) ? -1.0f : 0.0f);
    return s * r;
}
static __device__ __forceinline__ void cpasync16(void* dst_sm, const void* src) {
    unsigned d = (unsigned)__cvta_generic_to_shared(dst_sm);
    asm volatile("cp.async.cg.shared.global [%0], [%1], 16;" :: "r"(d), "l"(src));
}
// m16n8k8 tf32 mma, fp32 accumulate (base PTX, sm_80+ -> valid on sm_100)
static __device__ __forceinline__ void mma8(float* d, const unsigned* a,
                                            unsigned b0, unsigned b1) {
    asm volatile(
        "mma.sync.aligned.m16n8k8.row.col.f32.tf32.tf32.f32 "
        "{%0,%1,%2,%3}, {%4,%5,%6,%7}, {%8,%9}, {%0,%1,%2,%3};"
        : "+f"(d[0]), "+f"(d[1]), "+f"(d[2]), "+f"(d[3])
        : "r"(a[0]), "r"(a[1]), "r"(a[2]), "r"(a[3]), "r"(b0), "r"(b1));
}

// ---------------- generic warp-tiled GEMM stage -------------------------
// D[128][N] = A_sm[128][K]@B_g[K][N], B streamed in K-chunks of 16 (double-buffered
// cp.async). 16 warps: warp = (wid&3) M-tile of 32 rows x (wid>>2) N-slice of N/4.
// Epilogue epi(r, c, d[4]) gets elements (r,c),(r,c+1),(r+8,c),(r+8,c+1).
template <int N, int NCH, class Epi>
static __device__ __forceinline__ void gemm_stage(
    float* sm, int abase, const float* __restrict__ gB, int tid, Epi epi)
{
    constexpr int NT = N / 32;         // n-tiles (of 8) per warp
    constexpr int RQ = N / 4;          // 16B units per B row
    constexpr int UN = 16 * RQ;        // 16B units per chunk
    const int wid = tid >> 5, lane = tid & 31;
    const int g = lane >> 2, tg = lane & 3;
    const int mw = (wid & 3) * 32;
    const int ncol = (wid >> 2) * (N / 4);

    float acc[2][NT][4];
#pragma unroll
    for (int i = 0; i < 2; i++)
#pragma unroll
        for (int j = 0; j < NT; j++)
#pragma unroll
            for (int q = 0; q < 4; q++) acc[i][j][q] = 0.0f;

    // chunk loader: gmem rows contiguous -> smem rows at stride N+8 (≡8 mod 32)
    auto load_chunk = [&](int c, int buf) {
        const float* src = gB + (size_t)c * 16 * N;
        float* dst = sm + SM_BBUF + buf * BBUF_STRIDE;
#pragma unroll
        for (int u0 = 0; u0 < UN; u0 += 512) {
            int u = u0 + tid;
            if (u < UN) {
                int row = u / RQ, col = u - row * RQ;
                cpasync16(dst + row * (N + 8) + col * 4, src + row * N + col * 4);
            }
        }
        asm volatile("cp.async.commit_group;");
    };

    load_chunk(0, 0);
    for (int c = 0; c < NCH; c++) {
        if (c + 1 < NCH) {
            load_chunk(c + 1, (c + 1) & 1);
            asm volatile("cp.async.wait_group 1;");
        } else {
            asm volatile("cp.async.wait_group 0;");
        }
        __syncthreads();                       // chunk c visible to all
        const float* Bb = sm + SM_BBUF + (c & 1) * BBUF_STRIDE;
#pragma unroll
        for (int s = 0; s < 2; s++) {          // two k-steps of 8 per chunk
            const int k = abase + c * 16 + s * 8 + tg;
            unsigned a[2][4];
#pragma unroll
            for (int mt = 0; mt < 2; mt++) {
                const float* ap = sm + (mw + mt * 16 + g) * LDA + k;
                a[mt][0] = __float_as_uint(ap[0]);
                a[mt][1] = __float_as_uint(ap[8 * LDA]);
                a[mt][2] = __float_as_uint(ap[4]);
                a[mt][3] = __float_as_uint(ap[8 * LDA + 4]);
            }
#pragma unroll
            for (int nt = 0; nt < NT; nt++) {
                const float* bp = Bb + (s * 8 + tg) * (N + 8) + ncol + nt * 8 + g;
                unsigned b0 = __float_as_uint(bp[0]);
                unsigned b1 = __float_as_uint(bp[4 * (N + 8)]);
                mma8(acc[0][nt], a[0], b0, b1);
                mma8(acc[1][nt], a[1], b0, b1);
            }
        }
        __syncthreads();                       // all reads done before buffer reuse
    }
#pragma unroll
    for (int mt = 0; mt < 2; mt++)
#pragma unroll
        for (int nt = 0; nt < NT; nt++)
            epi(mw + mt * 16 + g, ncol + nt * 8 + tg * 2, acc[mt][nt]);
}

// ---------------- main fused kernel ----------------
__global__ void __launch_bounds__(512, 1) lista_mma(
    const float* __restrict__ x,  const float* __restrict__ cp,
    const float* __restrict__ wp,
    const float* __restrict__ b1, const float* __restrict__ b2,
    const float* __restrict__ b3, const float* __restrict__ W4,
    const float* __restrict__ b4)
{
    extern __shared__ float sm[];
    const int tid = threadIdx.x;
    const int img = blockIdx.z;
    const int pr0 = blockIdx.y * 16, pc0 = blockIdx.x * 8;
    const float cv = cp[0], wv = wp[0];
    const float* xi = x + img * 16384;
    float* bias = sm + SM_BIAS;
    float* thr  = bias + 256;

    if (tid < 128) bias[tid] = b1[tid];
    if (tid < 64)  bias[128 + tid] = b2[tid];
    if (tid < 32)  { bias[192 + tid] = b3[tid]; bias[224 + tid] = tf32r(W4[tid]); }

    // ---- U -> A cols [256,320), tf32-rounded, zero-padded outside image ----
    for (int idx = tid; idx < 8192; idx += 512) {
        int m = idx >> 6, d = idx & 63;
        int pr = pr0 + (m >> 3), pc = pc0 + (m & 7);
        float v = (pr < OH && pc < OH) ? xi[(pr + (d >> 3)) * 128 + pc + (d & 7)] : 0.0f;
        sm[m * LDA + ABASE_U + d] = tf32r(v);
    }
    // (ordering: first __syncthreads inside gemm_stage makes U/bias visible)

    // ---- h1 = relu(U@W1+b1) -> A cols [0,128) ----
    gemm_stage<128, 4>(sm, ABASE_U, g_Bh1, tid, [&](int r, int c, float* d) {
        sm[r * LDA + c]           = tf32r(fmaxf(d[0] + bias[c],     0.0f));
        sm[r * LDA + c + 1]       = tf32r(fmaxf(d[1] + bias[c + 1], 0.0f));
        sm[(r + 8) * LDA + c]     = tf32r(fmaxf(d[2] + bias[c],     0.0f));
        sm[(r + 8) * LDA + c + 1] = tf32r(fmaxf(d[3] + bias[c + 1], 0.0f));
    });

    // ---- h2 = relu(h1@W2+b2) -> A cols [128,192) ----
    gemm_stage<64, 8>(sm, 0, g_Bh2, tid, [&](int r, int c, float* d) {
        sm[r * LDA + 128 + c]           = tf32r(fmaxf(d[0] + bias[128 + c],     0.0f));
        sm[r * LDA + 128 + c + 1]       = tf32r(fmaxf(d[1] + bias[128 + c + 1], 0.0f));
        sm[(r + 8) * LDA + 128 + c]     = tf32r(fmaxf(d[2] + bias[128 + c],     0.0f));
        sm[(r + 8) * LDA + 128 + c + 1] = tf32r(fmaxf(d[3] + bias[128 + c + 1], 0.0f));
    });

    // ---- h3 = relu(h2@W3+b3) -> A cols [192,224) ----
    gemm_stage<32, 4>(sm, 128, g_Bh3, tid, [&](int r, int c, float* d) {
        sm[r * LDA + 192 + c]           = tf32r(fmaxf(d[0] + bias[192 + c],     0.0f));
        sm[r * LDA + 192 + c + 1]       = tf32r(fmaxf(d[1] + bias[192 + c + 1], 0.0f));
        sm[(r + 8) * LDA + 192 + c]     = tf32r(fmaxf(d[2] + bias[192 + c],     0.0f));
        sm[(r + 8) * LDA + 192 + c + 1] = tf32r(fmaxf(d[3] + bias[192 + c + 1], 0.0f));
    });
    __syncthreads();

    // ---- thr[m] = (h3[m]@W4 + b4) / c ----
    if (tid < 128) {
        float a = b4[0];
        const float* hm = sm + tid * LDA + 192;
#pragma unroll
        for (int j = 0; j < 32; j++) a = fmaf(hm[j], bias[224 + j], a);
        thr[tid] = a / cv;
    }
    // (thr visible via first sync inside next stage)

    // ---- y = U@Dict ; z0 = tf32(soft(y, thr)) -> A cols [0,256) ----
    gemm_stage<256, 4>(sm, ABASE_U, g_By, tid, [&](int r, int c, float* d) {
        float t0 = thr[r], t1 = thr[r + 8];
        sm[r * LDA + c]           = tf32r(softthr(d[0], t0));
        sm[r * LDA + c + 1]       = tf32r(softthr(d[1], t0));
        sm[(r + 8) * LDA + c]     = tf32r(softthr(d[2], t1));
        sm[(r + 8) * LDA + c + 1] = tf32r(softthr(d[3], t1));
    });

    // ---- 7x LISTA: z = soft([z|U] @ [S ; Dict/c], thr) (y/c fused into GEMM) ----
    for (int it = 0; it < 7; it++) {
        gemm_stage<256, 20>(sm, 0, g_Bls, tid, [&](int r, int c, float* d) {
            float t0 = thr[r], t1 = thr[r + 8];
            sm[r * LDA + c]           = tf32r(softthr(d[0], t0));
            sm[r * LDA + c + 1]       = tf32r(softthr(d[1], t0));
            sm[(r + 8) * LDA + c]     = tf32r(softthr(d[2], t1));
            sm[(r + 8) * LDA + c + 1] = tf32r(softthr(d[3], t1));
        });
    }

    // ---- x_pred = clip(z@Dict^T, 0, 1) * w -> g_XP ----
    gemm_stage<64, 16>(sm, 0, g_Bxp, tid, [&](int r, int c, float* d) {
        int pr = pr0 + (r >> 3), pc = pc0 + (r & 7);
        if (pr < OH && pc < OH) {
            float2 v;
            v.x = fminf(fmaxf(d[0], 0.0f), 1.0f) * wv;
            v.y = fminf(fmaxf(d[1], 0.0f), 1.0f) * wv;
            *(float2*)(g_XP + (size_t)(img * 16384 + pr * 128 + pc) * 64 + c) = v;
        }
        int r2 = r + 8;
        int pr2 = pr0 + (r2 >> 3), pc2 = pc0 + (r2 & 7);
        if (pr2 < OH && pc2 < OH) {
            float2 v;
            v.x = fminf(fmaxf(d[2], 0.0f), 1.0f) * wv;
            v.y = fminf(fmaxf(d[3], 0.0f), 1.0f) * wv;
            *(float2*)(g_XP + (size_t)(img * 16384 + pr2 * 128 + pc2) * 64 + c) = v;
        }
    });
}

// ---------------- prep: S block of B_ls ----------------
__global__ void prep_S(const float* __restrict__ Dict, const float* __restrict__ cp) {
    int k = blockIdx.x, n = threadIdx.x;
    float c = cp[0], s = 0.0f;
#pragma unroll 8
    for (int r = 0; r < 64; r++)
        s = fmaf(tf32r(Dict[r * 256 + k]), tf32r(Dict[r * 256 + n]), s);
    g_Bls[k * 256 + n] = tf32r((k == n ? 1.0f : 0.0f) - s / c);
}

// ---------------- prep: everything else (tf32 rounding / transpose) ------
__global__ void prep_misc(const float* __restrict__ Dict, const float* __restrict__ W1,
                          const float* __restrict__ W2, const float* __restrict__ W3,
                          const float* __restrict__ cp) {
    int idx = blockIdx.x * 256 + threadIdx.x;     // 64 blocks -> 16384 ids
    float c = cp[0];
    if (idx < 16384) {
        g_Bls[65536 + idx] = tf32r(Dict[idx] / c);           // rows 256..319 of B_ls
        g_By[idx] = tf32r(Dict[idx]);                        // Dict as B (y stage)
        int kk = idx >> 6, n = idx & 63;
        g_Bxp[idx] = tf32r(Dict[n * 256 + kk]);              // Dict^T (x_pred stage)
    }
    if (idx < 8192) {
        g_Bh1[idx] = tf32r(W1[idx]);
        g_Bh2[idx] = tf32r(W2[idx]);
    }
    if (idx < 2048) g_Bh3[idx] = tf32r(W3[idx]);
}

// ---------------- finalize: gather fold + analytic denominator -----------
__global__ void finalize_kernel(float* __restrict__ out, const float* __restrict__ wp) {
    int idx = blockIdx.x * 256 + threadIdx.x;
    int img = idx >> 14, i = (idx >> 7) & 127, j = idx & 127;
    float s = 0.0f;
#pragma unroll
    for (int di = 0; di < 8; di++) {
        int pr = i - di;
        if (pr < 0 || pr >= OH) continue;
#pragma unroll
        for (int dj = 0; dj < 8; dj++) {
            int pc = j - dj;
            if (pc < 0 || pc >= OH) continue;
            s += g_XP[(size_t)(img * 16384 + pr * 128 + pc) * 64 + di * 8 + dj];
        }
    }
    int ci = min(min(i + 1, 8), 128 - i);
    int cj = min(min(j + 1, 8), 128 - j);
    out[idx] = s / (wp[0] * (float)(ci * cj));
}

// ---------------- launch ----------------
extern "C" void kernel_launch(void* const* d_in, const int* in_sizes, int n_in,
                              void* d_out, int out_size) {
    const float* x    = (const float*)d_in[0];
    const float* Dict = (const float*)d_in[1];
    const float* c    = (const float*)d_in[2];
    const float* w    = (const float*)d_in[3];
    const float* W1   = (const float*)d_in[4];
    const float* b1   = (const float*)d_in[5];
    const float* W2   = (const float*)d_in[6];
    const float* b2   = (const float*)d_in[7];
    const float* W3   = (const float*)d_in[8];
    const float* b3   = (const float*)d_in[9];
    const float* W4   = (const float*)d_in[10];
    const float* b4   = (const float*)d_in[11];
    float* out = (float*)d_out;

    cudaFuncSetAttribute(lista_mma, cudaFuncAttributeMaxDynamicSharedMemorySize, SMEM_BYTES);

    prep_S<<<256, 256>>>(Dict, c);
    prep_misc<<<64, 256>>>(Dict, W1, W2, W3, c);
    lista_mma<<<dim3(16, 8, NIMG), 512, SMEM_BYTES>>>(x, c, w, b1, b2, b3, W4, b4);
    finalize_kernel<<<512, 256>>>(out, w);
}

// round 6
// speedup vs baseline: 7.5142x; 1.1045x over previous
#include <cuda_runtime.h>

#define OH 121
#define NIMG 8

// ---------------- smem float offsets ----------------
#define AF_OFF   0          // A in frag order: 8 mtiles x 40 k8 x 32 lanes x 4 = 40960
#define BB_OFF   40960      // 3 B-chunk buffers x 5120 floats
#define BIAS_OFF 56320      // b1[128] b2[64] b3[32] tf32(W4)[32]
#define THR_OFF  56576      // thr[128]
#define SM_FLOATS 56704
#define SMEM_BYTES (SM_FLOATS * 4)   // 226816 B

// ---------------- device scratch (B operands in frag order, tf32-rounded) ----
__device__ __align__(16) float g_Bls[320 * 256];  // [S ; Dict/c]
__device__ __align__(16) float g_Bh1[64 * 128];   // W1
__device__ __align__(16) float g_Bh2[128 * 64];   // W2
__device__ __align__(16) float g_Bh3[64 * 32];    // W3
__device__ __align__(16) float g_By [64 * 256];   // Dict
__device__ __align__(16) float g_Bxp[256 * 64];   // Dict^T
__device__ float g_XP[64 * NIMG * 128 * 128];     // x_pred, [d][img][pr][pc]

// ---------------- helpers ----------------
static __device__ __forceinline__ float tf32r(float v) {
    unsigned r;
    asm("cvt.rna.tf32.f32 %0, %1;" : "=r"(r) : "f"(v));
    return __uint_as_float(r);
}
static __device__ __forceinline__ float softthr(float v, float t) {
    float r = fmaxf(fabsf(v) - t, 0.0f);
    float s = (v > 0.0f) ? 1.0f : ((v < 0.0f) ? -1.0f : 0.0f);
    return s * r;
}
static __device__ __forceinline__ void cpasync16(void* dst_sm, const void* src) {
    unsigned d = (unsigned)__cvta_generic_to_shared(dst_sm);
    asm volatile("cp.async.cg.shared.global [%0], [%1], 16;" :: "r"(d), "l"(src));
}
static __device__ __forceinline__ void cpasync8(void* dst_sm, const void* src) {
    unsigned d = (unsigned)__cvta_generic_to_shared(dst_sm);
    asm volatile("cp.async.ca.shared.global [%0], [%1], 8;" :: "r"(d), "l"(src));
}
static __device__ __forceinline__ void mma8(float* d, const unsigned* a,
                                            unsigned b0, unsigned b1) {
    asm volatile(
        "mma.sync.aligned.m16n8k8.row.col.f32.tf32.tf32.f32 "
        "{%0,%1,%2,%3}, {%4,%5,%6,%7}, {%8,%9}, {%0,%1,%2,%3};"
        : "+f"(d[0]), "+f"(d[1]), "+f"(d[2]), "+f"(d[3])
        : "r"(a[0]), "r"(a[1]), "r"(a[2]), "r"(a[3]), "r"(b0), "r"(b1));
}

// A fragment address: element (row r in 0..127, abs col c in 0..319)
static __device__ __forceinline__ int af_idx(int r, int c) {
    return (((r >> 4) * 40 + (c >> 3)) * 32 + ((r & 7) << 2) + (c & 3)) * 4
           + ((r >> 3) & 1) + (((c >> 2) & 1) << 1);
}
// B fragment address in gmem (N = stage width): element B[k][n]
static __device__ __forceinline__ int fidx(int N, int k, int n) {
    int NT = N >> 5;
    int ns = n / (N >> 2), rem = n % (N >> 2);
    return (((k >> 3) * 4 + ns) * 32 + ((rem & 7) << 2) + (k & 3)) * (2 * NT)
           + ((rem >> 3) << 1) + ((k >> 2) & 1);
}

// ---------------- generic warp-tiled GEMM stage -------------------------
// D[128][N] = A_frag_sm[128][K] @ B_frag_gmem[K][N].
// 16 warps = 4 m-tiles(32 rows) x 4 n-slices(N/4). K-chunks of 16, 3-stage
// cp.async pipeline, ONE __syncthreads per chunk.
template <int N, int K, int AB8, bool PE, class Epi>
static __device__ __forceinline__ void gemm_stage(
    float* sm, const float* __restrict__ gB, int tid, Epi epi)
{
    constexpr int NT  = N / 32;
    constexpr int NT2 = (NT >= 2) ? NT / 2 : 1;
    constexpr int NCH = K / 16;
    const int wid = tid >> 5, lane = tid & 31;
    const int g = lane >> 2, tg = lane & 3;
    const int mt0  = (wid & 3) * 2;        // base 16-row tile index
    const int ns   = wid >> 2;
    const int ncol = ns * (N / 4);

    float acc[2][NT][4];
#pragma unroll
    for (int a = 0; a < 2; a++)
#pragma unroll
        for (int b = 0; b < NT; b++)
#pragma unroll
            for (int q = 0; q < 4; q++) acc[a][b][q] = 0.0f;

    float* bb = sm + BB_OFF;

    auto load_chunk = [&](int c) {
        float* dst = bb + (c % 3) * 5120;
        const float* src = gB + (size_t)c * (512 * NT);
        if (NT >= 2) {
            constexpr int P = 128 * NT;            // 16B pieces per chunk
#pragma unroll
            for (int p0 = 0; p0 < P; p0 += 512) {
                int p = p0 + tid;
                if ((P % 512 == 0) || p < P) {
                    int blk = p / NT2, pi = p % NT2;
                    cpasync16(dst + blk * 20 + pi * 4, src + blk * (2 * NT) + pi * 4);
                }
            }
        } else {
            if (tid < 256) cpasync8(dst + tid * 20, src + tid * 2);
        }
        asm volatile("cp.async.commit_group;");
    };

    load_chunk(0);
    load_chunk(1);

    for (int c = 0; c < NCH; c++) {
        if (c + 1 < NCH) asm volatile("cp.async.wait_group 1;");
        else             asm volatile("cp.async.wait_group 0;");
        __syncthreads();                 // chunk c visible; buf (c+2)%3 free
        if (c + 2 < NCH) load_chunk(c + 2);
        const float* bbuf = bb + (c % 3) * 5120;
#pragma unroll
        for (int s = 0; s < 2; s++) {
            const int k8 = AB8 + c * 2 + s;
            uint4 av[2];
#pragma unroll
            for (int mt = 0; mt < 2; mt++)
                av[mt] = *(const uint4*)(sm + (((mt0 + mt) * 40 + k8) * 32 + lane) * 4);
            float4 bv[NT2];
            const float4* bp = (const float4*)(bbuf + ((s * 4 + ns) * 32 + lane) * 20);
#pragma unroll
            for (int i = 0; i < NT2; i++) bv[i] = bp[i];
            const float* bf = (const float*)bv;
#pragma unroll
            for (int nt = 0; nt < NT; nt++) {
                unsigned b0 = __float_as_uint(bf[nt * 2]);
                unsigned b1 = __float_as_uint(bf[nt * 2 + 1]);
                mma8(acc[0][nt], (const unsigned*)&av[0], b0, b1);
                mma8(acc[1][nt], (const unsigned*)&av[1], b0, b1);
            }
        }
    }
    if (PE) __syncthreads();             // all reads done before in-place writes
#pragma unroll
    for (int mt = 0; mt < 2; mt++)
#pragma unroll
        for (int nt = 0; nt < NT; nt++)
            epi((mt0 + mt) * 16 + g, ncol + nt * 8 + tg * 2, acc[mt][nt]);
}

// ---------------- main fused kernel ----------------
__global__ void __launch_bounds__(512, 1) lista_mma(
    const float* __restrict__ x,  const float* __restrict__ cp,
    const float* __restrict__ wp,
    const float* __restrict__ b1, const float* __restrict__ b2,
    const float* __restrict__ b3, const float* __restrict__ W4,
    const float* __restrict__ b4)
{
    extern __shared__ float sm[];
    const int tid = threadIdx.x;
    const int img = blockIdx.z;
    const int pr0 = blockIdx.y * 16, pc0 = blockIdx.x * 8;
    const float cv = cp[0], wv = wp[0];
    const float* xi = x + img * 16384;
    float* bias = sm + BIAS_OFF;
    float* thr  = sm + THR_OFF;

    if (tid < 128) bias[tid] = b1[tid];
    if (tid < 64)  bias[128 + tid] = b2[tid];
    if (tid < 32)  { bias[192 + tid] = b3[tid]; bias[224 + tid] = tf32r(W4[tid]); }

    // ---- U -> A frag cols [256,320), tf32, zero-padded outside image ----
    for (int idx = tid; idx < 8192; idx += 512) {
        int m = idx >> 6, d = idx & 63;
        int pr = pr0 + (m >> 3), pc = pc0 + (m & 7);
        float v = (pr < OH && pc < OH) ? xi[(pr + (d >> 3)) * 128 + pc + (d & 7)] : 0.0f;
        sm[af_idx(m, 256 + d)] = tf32r(v);
    }
    // (first sync inside gemm_stage publishes U/bias)

    // ---- h1 = relu(U@W1+b1) -> cols [0,128) ----
    gemm_stage<128, 64, 32, false>(sm, g_Bh1, tid, [&](int r, int c, float* d) {
        sm[af_idx(r, c)]         = tf32r(fmaxf(d[0] + bias[c],     0.0f));
        sm[af_idx(r, c + 1)]     = tf32r(fmaxf(d[1] + bias[c + 1], 0.0f));
        sm[af_idx(r + 8, c)]     = tf32r(fmaxf(d[2] + bias[c],     0.0f));
        sm[af_idx(r + 8, c + 1)] = tf32r(fmaxf(d[3] + bias[c + 1], 0.0f));
    });

    // ---- h2 = relu(h1@W2+b2) -> cols [128,192) ----
    gemm_stage<64, 128, 0, false>(sm, g_Bh2, tid, [&](int r, int c, float* d) {
        sm[af_idx(r, 128 + c)]         = tf32r(fmaxf(d[0] + bias[128 + c],     0.0f));
        sm[af_idx(r, 128 + c + 1)]     = tf32r(fmaxf(d[1] + bias[128 + c + 1], 0.0f));
        sm[af_idx(r + 8, 128 + c)]     = tf32r(fmaxf(d[2] + bias[128 + c],     0.0f));
        sm[af_idx(r + 8, 128 + c + 1)] = tf32r(fmaxf(d[3] + bias[128 + c + 1], 0.0f));
    });

    // ---- h3 = relu(h2@W3+b3) -> cols [192,224) ----
    gemm_stage<32, 64, 16, false>(sm, g_Bh3, tid, [&](int r, int c, float* d) {
        sm[af_idx(r, 192 + c)]         = tf32r(fmaxf(d[0] + bias[192 + c],     0.0f));
        sm[af_idx(r, 192 + c + 1)]     = tf32r(fmaxf(d[1] + bias[192 + c + 1], 0.0f));
        sm[af_idx(r + 8, 192 + c)]     = tf32r(fmaxf(d[2] + bias[192 + c],     0.0f));
        sm[af_idx(r + 8, 192 + c + 1)] = tf32r(fmaxf(d[3] + bias[192 + c + 1], 0.0f));
    });
    __syncthreads();

    // ---- thr[m] = (h3[m]@W4 + b4)/c ----
    if (tid < 128) {
        float a = b4[0];
#pragma unroll
        for (int j = 0; j < 32; j++) a = fmaf(sm[af_idx(tid, 192 + j)], bias[224 + j], a);
        thr[tid] = a / cv;
    }
    // (thr published by first sync of next stage; epi runs after that)

    // ---- y = U@Dict ; z0 = tf32(soft(y, thr)) -> cols [0,256) ----
    gemm_stage<256, 64, 32, false>(sm, g_By, tid, [&](int r, int c, float* d) {
        float t0 = thr[r], t1 = thr[r + 8];
        sm[af_idx(r, c)]         = tf32r(softthr(d[0], t0));
        sm[af_idx(r, c + 1)]     = tf32r(softthr(d[1], t0));
        sm[af_idx(r + 8, c)]     = tf32r(softthr(d[2], t1));
        sm[af_idx(r + 8, c + 1)] = tf32r(softthr(d[3], t1));
    });

    // ---- 7x LISTA: z = soft([z|U] @ [S ; Dict/c], thr) ----
    for (int it = 0; it < 7; it++) {
        gemm_stage<256, 320, 0, true>(sm, g_Bls, tid, [&](int r, int c, float* d) {
            float t0 = thr[r], t1 = thr[r + 8];
            sm[af_idx(r, c)]         = tf32r(softthr(d[0], t0));
            sm[af_idx(r, c + 1)]     = tf32r(softthr(d[1], t0));
            sm[af_idx(r + 8, c)]     = tf32r(softthr(d[2], t1));
            sm[af_idx(r + 8, c + 1)] = tf32r(softthr(d[3], t1));
        });
    }

    // ---- x_pred = clip(z@Dict^T, 0, 1)*w -> g_XP ([d][img][pix] planes) ----
    gemm_stage<64, 256, 0, false>(sm, g_Bxp, tid, [&](int r, int c, float* d) {
        int pr = pr0 + (r >> 3), pc = pc0 + (r & 7);
        if (pr < OH && pc < OH) {
            int gp = img * 16384 + pr * 128 + pc;
            g_XP[(size_t)c * 131072 + gp]       = fminf(fmaxf(d[0], 0.0f), 1.0f) * wv;
            g_XP[(size_t)(c + 1) * 131072 + gp] = fminf(fmaxf(d[1], 0.0f), 1.0f) * wv;
        }
        int r2 = r + 8;
        int pr2 = pr0 + (r2 >> 3), pc2 = pc0 + (r2 & 7);
        if (pr2 < OH && pc2 < OH) {
            int gp2 = img * 16384 + pr2 * 128 + pc2;
            g_XP[(size_t)c * 131072 + gp2]       = fminf(fmaxf(d[2], 0.0f), 1.0f) * wv;
            g_XP[(size_t)(c + 1) * 131072 + gp2] = fminf(fmaxf(d[3], 0.0f), 1.0f) * wv;
        }
    });
}

// ---------------- prep: S block of B_ls (frag order) ----------------
__global__ void prep_S(const float* __restrict__ Dict, const float* __restrict__ cp) {
    int k = blockIdx.x, n = threadIdx.x;
    float c = cp[0], s = 0.0f;
#pragma unroll 8
    for (int r = 0; r < 64; r++)
        s = fmaf(tf32r(Dict[r * 256 + k]), tf32r(Dict[r * 256 + n]), s);
    g_Bls[fidx(256, k, n)] = tf32r((k == n ? 1.0f : 0.0f) - s / c);
}

// ---------------- prep: all other B operands (frag order) ----------------
__global__ void prep_misc(const float* __restrict__ Dict, const float* __restrict__ W1,
                          const float* __restrict__ W2, const float* __restrict__ W3,
                          const float* __restrict__ cp) {
    int idx = blockIdx.x * 256 + threadIdx.x;     // 64 blocks -> 16384 ids
    float c = cp[0];
    if (idx < 16384) {
        int kk = idx >> 8, n = idx & 255;
        g_Bls[fidx(256, 256 + kk, n)] = tf32r(Dict[idx] / c);   // Dict/c rows of B_ls
        g_By[fidx(256, kk, n)] = tf32r(Dict[idx]);              // Dict (y stage)
        int k2 = idx >> 6, n2 = idx & 63;
        g_Bxp[fidx(64, k2, n2)] = tf32r(Dict[n2 * 256 + k2]);   // Dict^T (x_pred)
    }
    if (idx < 8192) {
        g_Bh1[fidx(128, idx >> 7, idx & 127)] = tf32r(W1[idx]);
        g_Bh2[fidx(64,  idx >> 6, idx & 63)]  = tf32r(W2[idx]);
    }
    if (idx < 2048)
        g_Bh3[fidx(32, idx >> 5, idx & 31)] = tf32r(W3[idx]);
}

// ---------------- finalize: coalesced gather fold + analytic denominator ----
__global__ void finalize_kernel(float* __restrict__ out, const float* __restrict__ wp) {
    int idx = blockIdx.x * 256 + threadIdx.x;
    int img = idx >> 14, i = (idx >> 7) & 127, j = idx & 127;
    int base = img * 16384;
    float s = 0.0f;
#pragma unroll
    for (int di = 0; di < 8; di++) {
        int pr = i - di;
        if (pr < 0 || pr >= OH) continue;
#pragma unroll
        for (int dj = 0; dj < 8; dj++) {
            int pc = j - dj;
            if (pc < 0 || pc >= OH) continue;
            s += g_XP[(size_t)(di * 8 + dj) * 131072 + base + pr * 128 + pc];
        }
    }
    int ci = min(min(i + 1, 8), 128 - i);
    int cj = min(min(j + 1, 8), 128 - j);
    out[idx] = s / (wp[0] * (float)(ci * cj));
}

// ---------------- launch ----------------
extern "C" void kernel_launch(void* const* d_in, const int* in_sizes, int n_in,
                              void* d_out, int out_size) {
    const float* x    = (const float*)d_in[0];
    const float* Dict = (const float*)d_in[1];
    const float* c    = (const float*)d_in[2];
    const float* w    = (const float*)d_in[3];
    const float* W1   = (const float*)d_in[4];
    const float* b1   = (const float*)d_in[5];
    const float* W2   = (const float*)d_in[6];
    const float* b2   = (const float*)d_in[7];
    const float* W3   = (const float*)d_in[8];
    const float* b3   = (const float*)d_in[9];
    const float* W4   = (const float*)d_in[10];
    const float* b4   = (const float*)d_in[11];
    float* out = (float*)d_out;

    cudaFuncSetAttribute(lista_mma, cudaFuncAttributeMaxDynamicSharedMemorySize, SMEM_BYTES);

    prep_S<<<256, 256>>>(Dict, c);
    prep_misc<<<64, 256>>>(Dict, W1, W2, W3, c);
    lista_mma<<<dim3(16, 8, NIMG), 512, SMEM_BYTES>>>(x, c, w, b1, b2, b3, W4, b4);
    finalize_kernel<<<512, 256>>>(out, w);
}

// round 7
// speedup vs baseline: 15.5759x; 2.0729x over previous
#include <cuda_runtime.h>
#include <cuda_fp16.h>

#define OH 121
#define NIMG 8

// ---------------- smem layout (b32 word offsets) ----------------
// A frags (fp16): 8 mtiles x 20 k16-groups x 32 lanes x 4 words = 20480 words (80KB)
#define BB_OFF    20480      // 3 B-chunk buffers x 4096 words (16KB each)
#define BIAS_OFF  32768      // b1[128] b2[64] b3[32] w4[32] (fp32)
#define THR_OFF   33024      // thr[128] fp32
#define SM_WORDS  33152
#define SMEM_BYTES (SM_WORDS * 4)    // 132608 B

// ---------------- device scratch: B operands fp16, frag-ordered ----------
__device__ __align__(16) __half g_Bls[320 * 256];  // [S ; Dict/c]
__device__ __align__(16) __half g_Bh1[64 * 128];   // W1
__device__ __align__(16) __half g_Bh2[128 * 64];   // W2
__device__ __align__(16) __half g_Bh3[64 * 32];    // W3
__device__ __align__(16) __half g_By [64 * 256];   // Dict
__device__ __align__(16) __half g_Bxp[256 * 64];   // Dict^T
__device__ float g_XP[64 * NIMG * 128 * 128];      // x_pred, [d][img][pix]

// ---------------- helpers ----------------
static __device__ __forceinline__ float r16(float v) {      // fp16 rounding (tf32-equiv mantissa)
    return __half2float(__float2half_rn(v));
}
static __device__ __forceinline__ float softthr(float v, float t) {
    float r = fmaxf(fabsf(v) - t, 0.0f);
    float s = (v > 0.0f) ? 1.0f : ((v < 0.0f) ? -1.0f : 0.0f);
    return s * r;
}
static __device__ __forceinline__ void cpasync16(void* dst_sm, const void* src) {
    unsigned d = (unsigned)__cvta_generic_to_shared(dst_sm);
    asm volatile("cp.async.cg.shared.global [%0], [%1], 16;" :: "r"(d), "l"(src));
}
// m16n8k16 fp16 mma, fp32 accumulate
static __device__ __forceinline__ void mma16(float* d, const unsigned* a,
                                             unsigned b0, unsigned b1) {
    asm volatile(
        "mma.sync.aligned.m16n8k16.row.col.f32.f16.f16.f32 "
        "{%0,%1,%2,%3}, {%4,%5,%6,%7}, {%8,%9}, {%0,%1,%2,%3};"
        : "+f"(d[0]), "+f"(d[1]), "+f"(d[2]), "+f"(d[3])
        : "r"(a[0]), "r"(a[1]), "r"(a[2]), "r"(a[3]), "r"(b0), "r"(b1));
}

// A fragment b32-word address for element (r, c); c must be even
static __device__ __forceinline__ int af_word(int r, int c) {
    return (((r >> 4) * 20 + (c >> 4)) * 32 + ((r & 7) << 2) + ((c & 7) >> 1)) * 4
           + ((r >> 3) & 1) + (((c >> 3) & 1) << 1);
}
static __device__ __forceinline__ int af_half(int r, int c) {
    return af_word(r, c & ~1) * 2 + (c & 1);
}
// B fragment half-index in gmem for stage width N: element B[k][n]
static __device__ __forceinline__ int fidx_h(int N, int k, int n) {
    int NT = N >> 5;
    int chunk = k >> 5, s = (k >> 4) & 1, kk = k & 15;
    int tg = (kk >> 1) & 3, regk = (kk >> 3) & 1;
    int Nq = N >> 2, ns = n / Nq, rem = n % Nq, nt = rem >> 3, g = rem & 7;
    int lane = (g << 2) | tg;
    int word;
    if (NT >= 2) {
        int w = nt * 2 + regk, p = w >> 2, j = w & 3;
        word = chunk * 16 * N + (s * 4 + ns) * (NT * 64) + p * 128 + lane * 4 + j;
    } else {
        word = chunk * 512 + (s * 4 + ns) * 64 + lane * 2 + regk;
    }
    return word * 2 + (k & 1);
}

// ---------------- generic warp-tiled fp16 GEMM stage --------------------
// D[128][N] = A_frag_sm[128][K] @ B_frag_gmem[K][N], fp32 accum.
// 16 warps = 4 mtiles(32 rows) x 4 n-slices(N/4). K-chunks of 32 (2 k16 steps),
// 3-stage cp.async pipeline, one barrier per chunk + trailing barrier.
template <int N, int K, int AB16, bool PE, class Epi>
static __device__ __forceinline__ void gemm_stage(
    float* sm, const __half* __restrict__ gB, int tid, Epi epi)
{
    constexpr int NT  = N / 32;
    constexpr int NT2 = (NT >= 2) ? NT / 2 : 1;
    constexpr int NCH = K / 32;
    constexpr int P   = 4 * N;                   // uint4 pieces per chunk
    const int wid = tid >> 5, lane = tid & 31;
    const int g = lane >> 2, tg = lane & 3;
    const int mt0  = (wid & 3) * 2;
    const int ns   = wid >> 2;
    const int ncol = ns * (N / 4);

    float acc[2][NT][4];
#pragma unroll
    for (int a = 0; a < 2; a++)
#pragma unroll
        for (int b = 0; b < NT; b++)
#pragma unroll
            for (int q = 0; q < 4; q++) acc[a][b][q] = 0.0f;

    const uint4* gB4 = (const uint4*)gB;
    uint4* bb4 = (uint4*)(sm + BB_OFF);
    const uint4* A4 = (const uint4*)sm;

    auto load_chunk = [&](int c) {
        const uint4* src = gB4 + (size_t)c * P;
        uint4* dst = bb4 + (c % 3) * 1024;
#pragma unroll
        for (int p0 = 0; p0 < P; p0 += 512) {
            int p = p0 + tid;
            if ((P % 512 == 0) || p < P) cpasync16(dst + p, src + p);
        }
        asm volatile("cp.async.commit_group;");
    };

    load_chunk(0);
    load_chunk(1);

    for (int c = 0; c < NCH; c++) {
        if (c + 1 < NCH) asm volatile("cp.async.wait_group 1;");
        else             asm volatile("cp.async.wait_group 0;");
        __syncthreads();                 // chunk c visible; buf (c+2)%3 free
        if (c + 2 < NCH) load_chunk(c + 2);
        const uint4* bbuf4 = bb4 + (c % 3) * 1024;
#pragma unroll
        for (int s = 0; s < 2; s++) {
            const int q = AB16 + c * 2 + s;
            uint4 av[2];
#pragma unroll
            for (int mt = 0; mt < 2; mt++)
                av[mt] = A4[((mt0 + mt) * 20 + q) * 32 + lane];
            unsigned bw[2 * NT];
            if (NT >= 2) {
                uint4* bv = (uint4*)bw;
#pragma unroll
                for (int p = 0; p < NT2; p++)
                    bv[p] = bbuf4[(s * 4 + ns) * (NT * 16) + p * 32 + lane];
            } else {
                uint2 b2 = ((const uint2*)bbuf4)[(s * 4 + ns) * 32 + lane];
                bw[0] = b2.x; bw[1] = b2.y;
            }
#pragma unroll
            for (int nt = 0; nt < NT; nt++) {
                mma16(acc[0][nt], (const unsigned*)&av[0], bw[nt * 2], bw[nt * 2 + 1]);
                mma16(acc[1][nt], (const unsigned*)&av[1], bw[nt * 2], bw[nt * 2 + 1]);
            }
        }
    }
    if (PE) __syncthreads();             // in-place: all reads done before writes
#pragma unroll
    for (int mt = 0; mt < 2; mt++)
#pragma unroll
        for (int nt = 0; nt < NT; nt++)
            epi((mt0 + mt) * 16 + g, ncol + nt * 8 + tg * 2, acc[mt][nt]);
    __syncthreads();                     // publish epi writes; protect B bufs
}

// ---------------- main fused kernel ----------------
__global__ void __launch_bounds__(512, 1) lista_mma(
    const float* __restrict__ x,  const float* __restrict__ cp,
    const float* __restrict__ wp,
    const float* __restrict__ b1, const float* __restrict__ b2,
    const float* __restrict__ b3, const float* __restrict__ W4,
    const float* __restrict__ b4)
{
    extern __shared__ float sm[];
    __half2* smh2 = (__half2*)sm;
    __half*  smh  = (__half*)sm;
    const int tid = threadIdx.x;
    const int img = blockIdx.z;
    const int pr0 = blockIdx.y * 16, pc0 = blockIdx.x * 8;
    const float cv = cp[0], wv = wp[0];
    const float* xi = x + img * 16384;
    float* bias = sm + BIAS_OFF;
    float* thr  = sm + THR_OFF;

    if (tid < 128) bias[tid] = b1[tid];
    if (tid < 64)  bias[128 + tid] = b2[tid];
    if (tid < 32)  { bias[192 + tid] = b3[tid]; bias[224 + tid] = r16(W4[tid]); }

    // ---- U -> A frag cols [256,320), fp16, zero-padded outside image ----
    for (int idx = tid; idx < 8192; idx += 512) {
        int m = idx >> 6, d = idx & 63;
        int pr = pr0 + (m >> 3), pc = pc0 + (m & 7);
        float v = (pr < OH && pc < OH) ? xi[(pr + (d >> 3)) * 128 + pc + (d & 7)] : 0.0f;
        smh[af_half(m, 256 + d)] = __float2half_rn(v);
    }
    // (first barrier inside gemm_stage publishes U/bias)

    // ---- h1 = relu(U@W1+b1) -> cols [0,128) ----
    gemm_stage<128, 64, 16, false>(sm, g_Bh1, tid, [&](int r, int c, float* d) {
        smh2[af_word(r, c)] = __floats2half2_rn(fmaxf(d[0] + bias[c], 0.0f),
                                                fmaxf(d[1] + bias[c + 1], 0.0f));
        smh2[af_word(r + 8, c)] = __floats2half2_rn(fmaxf(d[2] + bias[c], 0.0f),
                                                    fmaxf(d[3] + bias[c + 1], 0.0f));
    });

    // ---- h2 = relu(h1@W2+b2) -> cols [128,192) ----
    gemm_stage<64, 128, 0, false>(sm, g_Bh2, tid, [&](int r, int c, float* d) {
        int cc = 128 + c;
        smh2[af_word(r, cc)] = __floats2half2_rn(fmaxf(d[0] + bias[cc], 0.0f),
                                                 fmaxf(d[1] + bias[cc + 1], 0.0f));
        smh2[af_word(r + 8, cc)] = __floats2half2_rn(fmaxf(d[2] + bias[cc], 0.0f),
                                                     fmaxf(d[3] + bias[cc + 1], 0.0f));
    });

    // ---- h3 = relu(h2@W3+b3) -> cols [192,224) ----
    gemm_stage<32, 64, 8, false>(sm, g_Bh3, tid, [&](int r, int c, float* d) {
        int cc = 192 + c;
        smh2[af_word(r, cc)] = __floats2half2_rn(fmaxf(d[0] + bias[cc], 0.0f),
                                                 fmaxf(d[1] + bias[cc + 1], 0.0f));
        smh2[af_word(r + 8, cc)] = __floats2half2_rn(fmaxf(d[2] + bias[cc], 0.0f),
                                                     fmaxf(d[3] + bias[cc + 1], 0.0f));
    });

    // ---- thr[m] = (h3[m]@W4 + b4)/c ----
    if (tid < 128) {
        float a = b4[0];
#pragma unroll
        for (int j = 0; j < 32; j++)
            a = fmaf(__half2float(smh[af_half(tid, 192 + j)]), bias[224 + j], a);
        thr[tid] = a / cv;
    }
    // (published by first barrier of next stage; read only in its epilogue)

    // ---- y = U@Dict ; z0 = soft(y, thr) -> cols [0,256) ----
    gemm_stage<256, 64, 16, false>(sm, g_By, tid, [&](int r, int c, float* d) {
        float t0 = thr[r], t1 = thr[r + 8];
        smh2[af_word(r, c)]     = __floats2half2_rn(softthr(d[0], t0), softthr(d[1], t0));
        smh2[af_word(r + 8, c)] = __floats2half2_rn(softthr(d[2], t1), softthr(d[3], t1));
    });

    // ---- 7x LISTA: z = soft([z|U] @ [S ; Dict/c], thr) ----
    for (int it = 0; it < 7; it++) {
        gemm_stage<256, 320, 0, true>(sm, g_Bls, tid, [&](int r, int c, float* d) {
            float t0 = thr[r], t1 = thr[r + 8];
            smh2[af_word(r, c)]     = __floats2half2_rn(softthr(d[0], t0), softthr(d[1], t0));
            smh2[af_word(r + 8, c)] = __floats2half2_rn(softthr(d[2], t1), softthr(d[3], t1));
        });
    }

    // ---- x_pred = clip(z@Dict^T, 0, 1)*w -> g_XP ([d][img][pix] planes) ----
    gemm_stage<64, 256, 0, false>(sm, g_Bxp, tid, [&](int r, int c, float* d) {
        int pr = pr0 + (r >> 3), pc = pc0 + (r & 7);
        if (pr < OH && pc < OH) {
            int gp = img * 16384 + pr * 128 + pc;
            g_XP[(size_t)c * 131072 + gp]       = fminf(fmaxf(d[0], 0.0f), 1.0f) * wv;
            g_XP[(size_t)(c + 1) * 131072 + gp] = fminf(fmaxf(d[1], 0.0f), 1.0f) * wv;
        }
        int r2 = r + 8;
        int pr2 = pr0 + (r2 >> 3), pc2 = pc0 + (r2 & 7);
        if (pr2 < OH && pc2 < OH) {
            int gp2 = img * 16384 + pr2 * 128 + pc2;
            g_XP[(size_t)c * 131072 + gp2]       = fminf(fmaxf(d[2], 0.0f), 1.0f) * wv;
            g_XP[(size_t)(c + 1) * 131072 + gp2] = fminf(fmaxf(d[3], 0.0f), 1.0f) * wv;
        }
    });
}

// ---------------- prep: S block of B_ls (fp16 frag order) ----------------
__global__ void prep_S(const float* __restrict__ Dict, const float* __restrict__ cp) {
    int k = blockIdx.x, n = threadIdx.x;
    float c = cp[0], s = 0.0f;
#pragma unroll 8
    for (int r = 0; r < 64; r++)
        s = fmaf(r16(Dict[r * 256 + k]), r16(Dict[r * 256 + n]), s);
    g_Bls[fidx_h(256, k, n)] = __float2half_rn((k == n ? 1.0f : 0.0f) - s / c);
}

// ---------------- prep: all other B operands ----------------
__global__ void prep_misc(const float* __restrict__ Dict, const float* __restrict__ W1,
                          const float* __restrict__ W2, const float* __restrict__ W3,
                          const float* __restrict__ cp) {
    int idx = blockIdx.x * 256 + threadIdx.x;     // 64 blocks -> 16384 ids
    float c = cp[0];
    if (idx < 16384) {
        int kk = idx >> 8, n = idx & 255;
        g_Bls[fidx_h(256, 256 + kk, n)] = __float2half_rn(Dict[idx] / c);
        g_By[fidx_h(256, kk, n)] = __float2half_rn(Dict[idx]);
        int k2 = idx >> 6, n2 = idx & 63;
        g_Bxp[fidx_h(64, k2, n2)] = __float2half_rn(Dict[n2 * 256 + k2]);
    }
    if (idx < 8192) {
        g_Bh1[fidx_h(128, idx >> 7, idx & 127)] = __float2half_rn(W1[idx]);
        g_Bh2[fidx_h(64,  idx >> 6, idx & 63)]  = __float2half_rn(W2[idx]);
    }
    if (idx < 2048)
        g_Bh3[fidx_h(32, idx >> 5, idx & 31)] = __float2half_rn(W3[idx]);
}

// ---------------- finalize: coalesced gather fold + analytic denominator ----
__global__ void finalize_kernel(float* __restrict__ out, const float* __restrict__ wp) {
    int idx = blockIdx.x * 256 + threadIdx.x;
    int img = idx >> 14, i = (idx >> 7) & 127, j = idx & 127;
    int base = img * 16384;
    float s = 0.0f;
#pragma unroll
    for (int di = 0; di < 8; di++) {
        int pr = i - di;
        if (pr < 0 || pr >= OH) continue;
#pragma unroll
        for (int dj = 0; dj < 8; dj++) {
            int pc = j - dj;
            if (pc < 0 || pc >= OH) continue;
            s += g_XP[(size_t)(di * 8 + dj) * 131072 + base + pr * 128 + pc];
        }
    }
    int ci = min(min(i + 1, 8), 128 - i);
    int cj = min(min(j + 1, 8), 128 - j);
    out[idx] = s / (wp[0] * (float)(ci * cj));
}

// ---------------- launch ----------------
extern "C" void kernel_launch(void* const* d_in, const int* in_sizes, int n_in,
                              void* d_out, int out_size) {
    const float* x    = (const float*)d_in[0];
    const float* Dict = (const float*)d_in[1];
    const float* c    = (const float*)d_in[2];
    const float* w    = (const float*)d_in[3];
    const float* W1   = (const float*)d_in[4];
    const float* b1   = (const float*)d_in[5];
    const float* W2   = (const float*)d_in[6];
    const float* b2   = (const float*)d_in[7];
    const float* W3   = (const float*)d_in[8];
    const float* b3   = (const float*)d_in[9];
    const float* W4   = (const float*)d_in[10];
    const float* b4   = (const float*)d_in[11];
    float* out = (float*)d_out;

    cudaFuncSetAttribute(lista_mma, cudaFuncAttributeMaxDynamicSharedMemorySize, SMEM_BYTES);

    prep_S<<<256, 256>>>(Dict, c);
    prep_misc<<<64, 256>>>(Dict, W1, W2, W3, c);
    lista_mma<<<dim3(16, 8, NIMG), 512, SMEM_BYTES>>>(x, c, w, b1, b2, b3, W4, b4);
    finalize_kernel<<<512, 256>>>(out, w);
}

// round 8
// speedup vs baseline: 17.2626x; 1.1083x over previous
#include <cuda_runtime.h>
#include <cuda_fp16.h>

#define OH 121
#define NIMG 8

// ---------------- smem layout (b32 word offsets), per 256-thread CTA ------
// A frags (fp16): 4 mtiles x 20 k16-groups x 32 lanes x 4 words = 10240 words (40KB)
#define BB_OFF    10240      // 3 B-chunk buffers x 4096 words (16KB each)
#define THR_OFF   22528      // thr[64] fp32
#define SM_WORDS  22592
#define SMEM_BYTES (SM_WORDS * 4)    // 90368 B -> 2 CTAs/SM

// ---------------- device scratch: B operands fp16, frag-ordered ----------
__device__ __align__(16) __half g_Bls[320 * 256];  // [S ; Dict/c]
__device__ __align__(16) __half g_Bh1[64 * 128];   // W1
__device__ __align__(16) __half g_Bh2[128 * 64];   // W2
__device__ __align__(16) __half g_Bh3[64 * 32];    // W3
__device__ __align__(16) __half g_By [64 * 256];   // Dict
__device__ __align__(16) __half g_Bxp[256 * 64];   // Dict^T
__device__ float g_XP[64 * NIMG * 128 * 128];      // x_pred, [d][img][pix]

// ---------------- helpers ----------------
static __device__ __forceinline__ float r16(float v) {
    return __half2float(__float2half_rn(v));
}
static __device__ __forceinline__ float softthr(float v, float t) {
    float r = fmaxf(fabsf(v) - t, 0.0f);
    float s = (v > 0.0f) ? 1.0f : ((v < 0.0f) ? -1.0f : 0.0f);
    return s * r;
}
static __device__ __forceinline__ void cpasync16(void* dst_sm, const void* src) {
    unsigned d = (unsigned)__cvta_generic_to_shared(dst_sm);
    asm volatile("cp.async.cg.shared.global [%0], [%1], 16;" :: "r"(d), "l"(src));
}
static __device__ __forceinline__ void mma16(float* d, const unsigned* a,
                                             unsigned b0, unsigned b1) {
    asm volatile(
        "mma.sync.aligned.m16n8k16.row.col.f32.f16.f16.f32 "
        "{%0,%1,%2,%3}, {%4,%5,%6,%7}, {%8,%9}, {%0,%1,%2,%3};"
        : "+f"(d[0]), "+f"(d[1]), "+f"(d[2]), "+f"(d[3])
        : "r"(a[0]), "r"(a[1]), "r"(a[2]), "r"(a[3]), "r"(b0), "r"(b1));
}

// A fragment b32-word address for element (r in 0..63, c in 0..319); c even
static __device__ __forceinline__ int af_word(int r, int c) {
    return (((r >> 4) * 20 + (c >> 4)) * 32 + ((r & 7) << 2) + ((c & 7) >> 1)) * 4
           + ((r >> 3) & 1) + (((c >> 3) & 1) << 1);
}
static __device__ __forceinline__ int af_half(int r, int c) {
    return af_word(r, c & ~1) * 2 + (c & 1);
}
// B fragment half-index in gmem for stage width N: element B[k][n] (unchanged)
static __device__ __forceinline__ int fidx_h(int N, int k, int n) {
    int NT = N >> 5;
    int chunk = k >> 5, s = (k >> 4) & 1, kk = k & 15;
    int tg = (kk >> 1) & 3, regk = (kk >> 3) & 1;
    int Nq = N >> 2, ns = n / Nq, rem = n % Nq, nt = rem >> 3, g = rem & 7;
    int lane = (g << 2) | tg;
    int word;
    if (NT >= 2) {
        int w = nt * 2 + regk, p = w >> 2, j = w & 3;
        word = chunk * 16 * N + (s * 4 + ns) * (NT * 64) + p * 128 + lane * 4 + j;
    } else {
        word = chunk * 512 + (s * 4 + ns) * 64 + lane * 2 + regk;
    }
    return word * 2 + (k & 1);
}

// ---------------- warp-tiled fp16 GEMM stage (256 threads, M=64) ---------
// D[64][N] = A_frag_sm[64][K] @ B_frag_gmem[K][N], fp32 accum.
// 8 warps = 2 m-halves(2 mtiles each) x 4 n-slices(N/4). K-chunks of 32,
// 3-stage cp.async pipeline, one barrier per chunk + trailing barrier.
template <int N, int K, int AB16, bool PE, class Epi>
static __device__ __forceinline__ void gemm_stage(
    float* sm, const __half* __restrict__ gB, int tid, Epi epi)
{
    constexpr int NT  = N / 32;
    constexpr int NT2 = (NT >= 2) ? NT / 2 : 1;
    constexpr int NCH = K / 32;
    constexpr int P   = 4 * N;                   // uint4 pieces per chunk
    const int wid = tid >> 5, lane = tid & 31;
    const int g = lane >> 2, tg = lane & 3;
    const int mt0  = (wid & 1) * 2;
    const int ns   = wid >> 1;
    const int ncol = ns * (N / 4);

    float acc[2][NT][4];
#pragma unroll
    for (int a = 0; a < 2; a++)
#pragma unroll
        for (int b = 0; b < NT; b++)
#pragma unroll
            for (int q = 0; q < 4; q++) acc[a][b][q] = 0.0f;

    const uint4* gB4 = (const uint4*)gB;
    uint4* bb4 = (uint4*)(sm + BB_OFF);
    const uint4* A4 = (const uint4*)sm;

    auto load_chunk = [&](int c) {
        const uint4* src = gB4 + (size_t)c * P;
        uint4* dst = bb4 + (c % 3) * 1024;
#pragma unroll
        for (int p0 = 0; p0 < P; p0 += 256) {
            int p = p0 + tid;
            if ((P % 256 == 0) || p < P) cpasync16(dst + p, src + p);
        }
        asm volatile("cp.async.commit_group;");
    };

    load_chunk(0);
    load_chunk(1);

    for (int c = 0; c < NCH; c++) {
        if (c + 1 < NCH) asm volatile("cp.async.wait_group 1;");
        else             asm volatile("cp.async.wait_group 0;");
        __syncthreads();                 // chunk c visible; buf (c+2)%3 free
        if (c + 2 < NCH) load_chunk(c + 2);
        const uint4* bbuf4 = bb4 + (c % 3) * 1024;
#pragma unroll
        for (int s = 0; s < 2; s++) {
            const int q = AB16 + c * 2 + s;
            uint4 av[2];
#pragma unroll
            for (int mt = 0; mt < 2; mt++)
                av[mt] = A4[((mt0 + mt) * 20 + q) * 32 + lane];
            unsigned bw[2 * NT];
            if (NT >= 2) {
                uint4* bv = (uint4*)bw;
#pragma unroll
                for (int p = 0; p < NT2; p++)
                    bv[p] = bbuf4[(s * 4 + ns) * (NT * 16) + p * 32 + lane];
            } else {
                uint2 b2 = ((const uint2*)bbuf4)[(s * 4 + ns) * 32 + lane];
                bw[0] = b2.x; bw[1] = b2.y;
            }
#pragma unroll
            for (int nt = 0; nt < NT; nt++) {
                mma16(acc[0][nt], (const unsigned*)&av[0], bw[nt * 2], bw[nt * 2 + 1]);
                mma16(acc[1][nt], (const unsigned*)&av[1], bw[nt * 2], bw[nt * 2 + 1]);
            }
        }
    }
    if (PE) __syncthreads();             // in-place: all reads done before writes
#pragma unroll
    for (int mt = 0; mt < 2; mt++)
#pragma unroll
        for (int nt = 0; nt < NT; nt++)
            epi((mt0 + mt) * 16 + g, ncol + nt * 8 + tg * 2, acc[mt][nt]);
    __syncthreads();                     // publish epi writes; protect B bufs
}

// ---------------- main fused kernel (256 thr, 64 patches/CTA) ------------
__global__ void __launch_bounds__(256, 2) lista_mma(
    const float* __restrict__ x,  const float* __restrict__ cp,
    const float* __restrict__ wp,
    const float* __restrict__ b1, const float* __restrict__ b2,
    const float* __restrict__ b3, const float* __restrict__ W4,
    const float* __restrict__ b4)
{
    extern __shared__ float sm[];
    __half2* smh2 = (__half2*)sm;
    __half*  smh  = (__half*)sm;
    const int tid = threadIdx.x;
    const int img = blockIdx.z;
    const int pr0 = blockIdx.y * 8, pc0 = blockIdx.x * 8;
    const float cv = cp[0], wv = wp[0];
    const float* xi = x + img * 16384;
    float* thr = sm + THR_OFF;

    // ---- U -> A frag cols [256,320), fp16, zero-padded outside image ----
    for (int idx = tid; idx < 4096; idx += 256) {
        int m = idx >> 6, d = idx & 63;
        int pr = pr0 + (m >> 3), pc = pc0 + (m & 7);
        float v = (pr < OH && pc < OH) ? xi[(pr + (d >> 3)) * 128 + pc + (d & 7)] : 0.0f;
        smh[af_half(m, 256 + d)] = __float2half_rn(v);
    }
    // (first barrier inside gemm_stage publishes U)

    // ---- h1 = relu(U@W1+b1) -> cols [0,128) ----
    gemm_stage<128, 64, 16, false>(sm, g_Bh1, tid, [&](int r, int c, float* d) {
        float bb0 = __ldg(b1 + c), bb1 = __ldg(b1 + c + 1);
        smh2[af_word(r, c)]     = __floats2half2_rn(fmaxf(d[0] + bb0, 0.0f),
                                                    fmaxf(d[1] + bb1, 0.0f));
        smh2[af_word(r + 8, c)] = __floats2half2_rn(fmaxf(d[2] + bb0, 0.0f),
                                                    fmaxf(d[3] + bb1, 0.0f));
    });

    // ---- h2 = relu(h1@W2+b2) -> cols [128,192) ----
    gemm_stage<64, 128, 0, false>(sm, g_Bh2, tid, [&](int r, int c, float* d) {
        float bb0 = __ldg(b2 + c), bb1 = __ldg(b2 + c + 1);
        int cc = 128 + c;
        smh2[af_word(r, cc)]     = __floats2half2_rn(fmaxf(d[0] + bb0, 0.0f),
                                                     fmaxf(d[1] + bb1, 0.0f));
        smh2[af_word(r + 8, cc)] = __floats2half2_rn(fmaxf(d[2] + bb0, 0.0f),
                                                     fmaxf(d[3] + bb1, 0.0f));
    });

    // ---- h3 = relu(h2@W3+b3) -> cols [192,224) ----
    gemm_stage<32, 64, 8, false>(sm, g_Bh3, tid, [&](int r, int c, float* d) {
        float bb0 = __ldg(b3 + c), bb1 = __ldg(b3 + c + 1);
        int cc = 192 + c;
        smh2[af_word(r, cc)]     = __floats2half2_rn(fmaxf(d[0] + bb0, 0.0f),
                                                     fmaxf(d[1] + bb1, 0.0f));
        smh2[af_word(r + 8, cc)] = __floats2half2_rn(fmaxf(d[2] + bb0, 0.0f),
                                                     fmaxf(d[3] + bb1, 0.0f));
    });

    // ---- thr[m] = (h3[m]@W4 + b4)/c ----
    if (tid < 64) {
        float a = b4[0];
#pragma unroll
        for (int j = 0; j < 32; j++)
            a = fmaf(__half2float(smh[af_half(tid, 192 + j)]), r16(__ldg(W4 + j)), a);
        thr[tid] = a / cv;
    }
    // (published by first barrier of next stage; read only in its epilogue)

    // ---- y = U@Dict ; z0 = soft(y, thr) -> cols [0,256) ----
    gemm_stage<256, 64, 16, false>(sm, g_By, tid, [&](int r, int c, float* d) {
        float t0 = thr[r], t1 = thr[r + 8];
        smh2[af_word(r, c)]     = __floats2half2_rn(softthr(d[0], t0), softthr(d[1], t0));
        smh2[af_word(r + 8, c)] = __floats2half2_rn(softthr(d[2], t1), softthr(d[3], t1));
    });

    // ---- 7x LISTA: z = soft([z|U] @ [S ; Dict/c], thr) ----
    for (int it = 0; it < 7; it++) {
        gemm_stage<256, 320, 0, true>(sm, g_Bls, tid, [&](int r, int c, float* d) {
            float t0 = thr[r], t1 = thr[r + 8];
            smh2[af_word(r, c)]     = __floats2half2_rn(softthr(d[0], t0), softthr(d[1], t0));
            smh2[af_word(r + 8, c)] = __floats2half2_rn(softthr(d[2], t1), softthr(d[3], t1));
        });
    }

    // ---- x_pred = clip(z@Dict^T, 0, 1)*w -> g_XP ([d][img][pix] planes) ----
    gemm_stage<64, 256, 0, false>(sm, g_Bxp, tid, [&](int r, int c, float* d) {
        int pr = pr0 + (r >> 3), pc = pc0 + (r & 7);
        if (pr < OH && pc < OH) {
            int gp = img * 16384 + pr * 128 + pc;
            g_XP[(size_t)c * 131072 + gp]       = fminf(fmaxf(d[0], 0.0f), 1.0f) * wv;
            g_XP[(size_t)(c + 1) * 131072 + gp] = fminf(fmaxf(d[1], 0.0f), 1.0f) * wv;
        }
        int r2 = r + 8;
        int pr2 = pr0 + (r2 >> 3), pc2 = pc0 + (r2 & 7);
        if (pr2 < OH && pc2 < OH) {
            int gp2 = img * 16384 + pr2 * 128 + pc2;
            g_XP[(size_t)c * 131072 + gp2]       = fminf(fmaxf(d[2], 0.0f), 1.0f) * wv;
            g_XP[(size_t)(c + 1) * 131072 + gp2] = fminf(fmaxf(d[3], 0.0f), 1.0f) * wv;
        }
    });
}

// ---------------- prep: S block of B_ls (fp16 frag order) ----------------
__global__ void prep_S(const float* __restrict__ Dict, const float* __restrict__ cp) {
    int k = blockIdx.x, n = threadIdx.x;
    float c = cp[0], s = 0.0f;
#pragma unroll 8
    for (int r = 0; r < 64; r++)
        s = fmaf(r16(Dict[r * 256 + k]), r16(Dict[r * 256 + n]), s);
    g_Bls[fidx_h(256, k, n)] = __float2half_rn((k == n ? 1.0f : 0.0f) - s / c);
}

// ---------------- prep: all other B operands ----------------
__global__ void prep_misc(const float* __restrict__ Dict, const float* __restrict__ W1,
                          const float* __restrict__ W2, const float* __restrict__ W3,
                          const float* __restrict__ cp) {
    int idx = blockIdx.x * 256 + threadIdx.x;     // 64 blocks -> 16384 ids
    float c = cp[0];
    if (idx < 16384) {
        int kk = idx >> 8, n = idx & 255;
        g_Bls[fidx_h(256, 256 + kk, n)] = __float2half_rn(Dict[idx] / c);
        g_By[fidx_h(256, kk, n)] = __float2half_rn(Dict[idx]);
        int k2 = idx >> 6, n2 = idx & 63;
        g_Bxp[fidx_h(64, k2, n2)] = __float2half_rn(Dict[n2 * 256 + k2]);
    }
    if (idx < 8192) {
        g_Bh1[fidx_h(128, idx >> 7, idx & 127)] = __float2half_rn(W1[idx]);
        g_Bh2[fidx_h(64,  idx >> 6, idx & 63)]  = __float2half_rn(W2[idx]);
    }
    if (idx < 2048)
        g_Bh3[fidx_h(32, idx >> 5, idx & 31)] = __float2half_rn(W3[idx]);
}

// ---------------- finalize: coalesced gather fold + analytic denominator ----
__global__ void finalize_kernel(float* __restrict__ out, const float* __restrict__ wp) {
    int idx = blockIdx.x * 256 + threadIdx.x;
    int img = idx >> 14, i = (idx >> 7) & 127, j = idx & 127;
    int base = img * 16384;
    float s = 0.0f;
#pragma unroll
    for (int di = 0; di < 8; di++) {
        int pr = i - di;
        if (pr < 0 || pr >= OH) continue;
#pragma unroll
        for (int dj = 0; dj < 8; dj++) {
            int pc = j - dj;
            if (pc < 0 || pc >= OH) continue;
            s += g_XP[(size_t)(di * 8 + dj) * 131072 + base + pr * 128 + pc];
        }
    }
    int ci = min(min(i + 1, 8), 128 - i);
    int cj = min(min(j + 1, 8), 128 - j);
    out[idx] = s / (wp[0] * (float)(ci * cj));
}

// ---------------- launch ----------------
extern "C" void kernel_launch(void* const* d_in, const int* in_sizes, int n_in,
                              void* d_out, int out_size) {
    const float* x    = (const float*)d_in[0];
    const float* Dict = (const float*)d_in[1];
    const float* c    = (const float*)d_in[2];
    const float* w    = (const float*)d_in[3];
    const float* W1   = (const float*)d_in[4];
    const float* b1   = (const float*)d_in[5];
    const float* W2   = (const float*)d_in[6];
    const float* b2   = (const float*)d_in[7];
    const float* W3   = (const float*)d_in[8];
    const float* b3   = (const float*)d_in[9];
    const float* W4   = (const float*)d_in[10];
    const float* b4   = (const float*)d_in[11];
    float* out = (float*)d_out;

    cudaFuncSetAttribute(lista_mma, cudaFuncAttributeMaxDynamicSharedMemorySize, SMEM_BYTES);

    prep_S<<<256, 256>>>(Dict, c);
    prep_misc<<<64, 256>>>(Dict, W1, W2, W3, c);
    lista_mma<<<dim3(16, 16, NIMG), 256, SMEM_BYTES>>>(x, c, w, b1, b2, b3, W4, b4);
    finalize_kernel<<<512, 256>>>(out, w);
}